// round 2
// baseline (speedup 1.0000x reference)
#include <cuda_runtime.h>
#include <math.h>

#define N_NODES 100000
#define N_EDGES 6400000
#define F_IN    128
#define F_OUT   16

// ---------------- device scratch (no allocations allowed) ----------------
__device__ float g_deg[N_NODES];                 // degree incl. self loop
__device__ float g_g  [N_NODES * F_OUT];         // dinv[n] * (x[n] @ W)
__device__ float g_acc[N_NODES * F_OUT];         // scatter accumulator

// ---------------- K0: reset all state (runs every call / replay) ----------
__global__ void __launch_bounds__(256) k_init(float* __restrict__ out) {
    int i = blockIdx.x * blockDim.x + threadIdx.x;
    int total4 = N_NODES * F_OUT / 4;            // 400000 float4 of acc
    if (i < total4) ((float4*)g_acc)[i] = make_float4(0.f, 0.f, 0.f, 0.f);
    if (i < N_NODES) g_deg[i] = 1.0f;            // self-loop contributes 1
    if (i < F_OUT) out[i] = 0.0f;
}

// ---------------- K1: degree of target nodes ------------------------------
__global__ void __launch_bounds__(256) k_degree(const int* __restrict__ dst) {
    int e = blockIdx.x * blockDim.x + threadIdx.x;
    if (e < N_EDGES) {
        atomicAdd(&g_deg[dst[e]], 1.0f);
    }
}

// ---------------- K2: g[n] = rsqrt(deg[n]) * (x[n] @ W) -------------------
__global__ void __launch_bounds__(128) k_gemm(const float* __restrict__ x,
                                              const float* __restrict__ W) {
    __shared__ float Ws[F_IN * F_OUT];
    for (int i = threadIdx.x; i < F_IN * F_OUT; i += blockDim.x) Ws[i] = W[i];
    __syncthreads();

    int n = blockIdx.x * blockDim.x + threadIdx.x;
    if (n >= N_NODES) return;

    const float4* x4 = (const float4*)(x + (size_t)n * F_IN);
    float acc[F_OUT];
#pragma unroll
    for (int f = 0; f < F_OUT; f++) acc[f] = 0.f;

#pragma unroll
    for (int k4 = 0; k4 < F_IN / 4; k4++) {
        float4 xv = x4[k4];
        int k = k4 * 4;
#pragma unroll
        for (int f = 0; f < F_OUT; f++) {
            acc[f] += xv.x * Ws[(k + 0) * F_OUT + f];
            acc[f] += xv.y * Ws[(k + 1) * F_OUT + f];
            acc[f] += xv.z * Ws[(k + 2) * F_OUT + f];
            acc[f] += xv.w * Ws[(k + 3) * F_OUT + f];
        }
    }
    float dinv = rsqrtf(g_deg[n]);
    float4* gg = (float4*)(g_g + (size_t)n * F_OUT);
#pragma unroll
    for (int q = 0; q < 4; q++) {
        gg[q] = make_float4(acc[q * 4 + 0] * dinv, acc[q * 4 + 1] * dinv,
                            acc[q * 4 + 2] * dinv, acc[q * 4 + 3] * dinv);
    }
}

// ---------------- K3: scatter g[src] into acc[dst] (4 threads / edge) -----
__global__ void __launch_bounds__(256) k_scatter(const int* __restrict__ src,
                                                 const int* __restrict__ dst) {
    long long t = (long long)blockIdx.x * blockDim.x + threadIdx.x;
    int e = (int)(t >> 2);
    int q = (int)(t & 3);
    if (e >= N_EDGES) return;
    int r = src[e];
    int c = dst[e];
    float4 v = ((const float4*)g_g)[r * 4 + q];
    float* p = g_acc + (size_t)c * F_OUT + q * 4;
    asm volatile("red.global.add.v4.f32 [%0], {%1,%2,%3,%4};"
                 :: "l"(p), "f"(v.x), "f"(v.y), "f"(v.z), "f"(v.w)
                 : "memory");
}

// ---------------- K4: out = mean_n tanh(dinv*(acc+g) + b) -----------------
__global__ void __launch_bounds__(256) k_finalize(const float* __restrict__ b,
                                                  float* __restrict__ out) {
    float bb[F_OUT];
#pragma unroll
    for (int f = 0; f < F_OUT; f++) bb[f] = b[f];

    float local[F_OUT];
#pragma unroll
    for (int f = 0; f < F_OUT; f++) local[f] = 0.f;

    const float invN = 1.0f / (float)N_NODES;
    for (int n = blockIdx.x * blockDim.x + threadIdx.x; n < N_NODES;
         n += gridDim.x * blockDim.x) {
        float dinv = rsqrtf(g_deg[n]);
        const float4* a4 = (const float4*)(g_acc + (size_t)n * F_OUT);
        const float4* g4 = (const float4*)(g_g + (size_t)n * F_OUT);
#pragma unroll
        for (int q = 0; q < 4; q++) {
            float4 a = a4[q];
            float4 g = g4[q];
            local[q * 4 + 0] += tanhf(dinv * (a.x + g.x) + bb[q * 4 + 0]);
            local[q * 4 + 1] += tanhf(dinv * (a.y + g.y) + bb[q * 4 + 1]);
            local[q * 4 + 2] += tanhf(dinv * (a.z + g.z) + bb[q * 4 + 2]);
            local[q * 4 + 3] += tanhf(dinv * (a.w + g.w) + bb[q * 4 + 3]);
        }
    }

    // warp butterfly reduction (all lanes end with the warp sum per f)
#pragma unroll
    for (int off = 16; off > 0; off >>= 1) {
#pragma unroll
        for (int f = 0; f < F_OUT; f++)
            local[f] += __shfl_xor_sync(0xFFFFFFFFu, local[f], off);
    }
    int lane = threadIdx.x & 31;
    if (lane < F_OUT) {
        atomicAdd(&out[lane], local[lane] * invN);
    }
}

// ---------------- launch ---------------------------------------------------
extern "C" void kernel_launch(void* const* d_in, const int* in_sizes, int n_in,
                              void* d_out, int out_size) {
    const float* x  = (const float*)d_in[0];
    const int*   ei = (const int*)d_in[1];   // [2, N_EDGES] int32 (JAX x64 off)
    const float* W  = (const float*)d_in[2];
    const float* b  = (const float*)d_in[3];
    float*       out = (float*)d_out;

    const int* src = ei;              // edge_index[0]
    const int* dst = ei + N_EDGES;    // edge_index[1]

    {   // K0: reset
        int total = N_NODES * F_OUT / 4;    // 400000 covers all resets
        k_init<<<(total + 255) / 256, 256>>>(out);
    }
    {   // K1: degrees
        k_degree<<<(N_EDGES + 255) / 256, 256>>>(dst);
    }
    {   // K2: gemm + dinv scale
        k_gemm<<<(N_NODES + 127) / 128, 128>>>(x, W);
    }
    {   // K3: scatter (4 threads per edge)
        long long threads = (long long)N_EDGES * 4;
        int blocks = (int)((threads + 255) / 256);
        k_scatter<<<blocks, 256>>>(src, dst);
    }
    {   // K4: finalize + mean pool
        k_finalize<<<592, 256>>>(b, out);
    }
}